// round 1
// baseline (speedup 1.0000x reference)
#include <cuda_runtime.h>
#include <cuda_bf16.h>
#include <math.h>

#define N_NODES 100000
#define N_EDGES 1600000
#define NFEAT 64
#define NHID 64
#define NCLASS 40

// ---------------- device scratch (no allocations allowed) ----------------
__device__ int2  g_edges[N_EDGES];            // (src, dst) as int32
__device__ float g_agg[N_NODES * NHID];       // aggregation buffer
__device__ float g_h[N_NODES * NHID];         // layer-1 output
__device__ float g_h2[N_NODES * NHID];        // layer-2 output
__device__ int   g_is64;                      // edge_index dtype flag

// ---------------- dtype sniff: int64 vs int32 edge_index ----------------
// Values are in [0, 100000). If stored as int64 (little-endian), every odd
// 32-bit word is 0. If int32, odd words are edge endpoints, ~never all zero.
__global__ void sniff_kernel(const unsigned int* __restrict__ w) {
    __shared__ int any;
    if (threadIdx.x == 0) any = 0;
    __syncthreads();
    unsigned int v = w[threadIdx.x * 2 + 1];  // sample 256 odd words
    if (v != 0u) atomicOr(&any, 1);
    __syncthreads();
    if (threadIdx.x == 0) g_is64 = (any == 0) ? 1 : 0;
}

__global__ void convert_kernel(const void* __restrict__ ei) {
    int e = blockIdx.x * blockDim.x + threadIdx.x;
    if (e >= N_EDGES) return;
    int s, d;
    if (g_is64) {
        const long long* p = (const long long*)ei;
        s = (int)p[e];
        d = (int)p[N_EDGES + e];
    } else {
        const int* p = (const int*)ei;
        s = p[e];
        d = p[N_EDGES + e];
    }
    g_edges[e] = make_int2(s, d);
}

// ---------------- zero the aggregation buffer ----------------
__global__ void zero_kernel(float4* __restrict__ buf, int n4) {
    int i = blockIdx.x * blockDim.x + threadIdx.x;
    if (i < n4) buf[i] = make_float4(0.f, 0.f, 0.f, 0.f);
}

// ---------------- edge scatter: agg[dst] += h[src] ----------------
// 16 threads per edge, one float4 (16B) each. red.global.add.v4.f32 keeps
// the atomic at sector granularity (4x fewer L2 atomic ops than scalar).
__global__ void scatter_kernel(const float* __restrict__ H, float* __restrict__ AGG) {
    long long idx = (long long)blockIdx.x * blockDim.x + threadIdx.x;
    if (idx >= (long long)N_EDGES * 16) return;
    int e = (int)(idx >> 4);
    int c = (int)(idx & 15);
    int2 ed = g_edges[e];
    float4 v = ((const float4*)H)[(long long)ed.x * 16 + c];
    float* p = &AGG[((long long)ed.y * 16 + c) * 4];
    asm volatile("red.global.add.v4.f32 [%0], {%1,%2,%3,%4};"
                 :: "l"(p), "f"(v.x), "f"(v.y), "f"(v.z), "f"(v.w)
                 : "memory");
}

// ---------------- fused (X + AGG) @ W[64,64] + b, ReLU ----------------
// Tile: 64 rows x 64 cols per block, 256 threads, each computes 4x4 outputs.
__global__ __launch_bounds__(256) void mlp64_kernel(
    const float* __restrict__ X, const float* __restrict__ AGG,
    const float* __restrict__ W, const float* __restrict__ B,
    float* __restrict__ OUT, int n)
{
    __shared__ float As[64][65];                 // padded for column reads
    __shared__ __align__(16) float Ws[64][64];
    __shared__ float Bs[64];

    int t = threadIdx.x;
    int row0 = blockIdx.x * 64;

    // load A tile = X + AGG (1024 float4 slots; each thread does 4)
    #pragma unroll
    for (int i = 0; i < 4; i++) {
        int idx = t + i * 256;          // float4 slot id
        int r = idx >> 4;               // row within tile
        int c4 = idx & 15;              // float4 within row
        int row = row0 + r;
        float4 xv = make_float4(0.f, 0.f, 0.f, 0.f);
        float4 av = xv;
        if (row < n) {
            xv = ((const float4*)X)[(long long)row * 16 + c4];
            av = ((const float4*)AGG)[(long long)row * 16 + c4];
        }
        As[r][c4 * 4 + 0] = xv.x + av.x;
        As[r][c4 * 4 + 1] = xv.y + av.y;
        As[r][c4 * 4 + 2] = xv.z + av.z;
        As[r][c4 * 4 + 3] = xv.w + av.w;
    }
    // load W tile
    #pragma unroll
    for (int i = 0; i < 4; i++) {
        int idx = t + i * 256;
        int r = idx >> 4;
        int c4 = idx & 15;
        ((float4*)&Ws[r][0])[c4] = ((const float4*)W)[idx];
    }
    if (t < 64) Bs[t] = B[t];
    __syncthreads();

    int tx = t & 15;        // col group: cols tx*4 .. tx*4+3
    int ty = t >> 4;        // row group: rows ty*4 .. ty*4+3

    float acc[4][4];
    #pragma unroll
    for (int i = 0; i < 4; i++)
        #pragma unroll
        for (int j = 0; j < 4; j++)
            acc[i][j] = Bs[tx * 4 + j];

    #pragma unroll
    for (int k = 0; k < 64; k++) {
        float4 b = *(const float4*)&Ws[k][tx * 4];
        float a0 = As[ty * 4 + 0][k];
        float a1 = As[ty * 4 + 1][k];
        float a2 = As[ty * 4 + 2][k];
        float a3 = As[ty * 4 + 3][k];
        acc[0][0] += a0 * b.x; acc[0][1] += a0 * b.y; acc[0][2] += a0 * b.z; acc[0][3] += a0 * b.w;
        acc[1][0] += a1 * b.x; acc[1][1] += a1 * b.y; acc[1][2] += a1 * b.z; acc[1][3] += a1 * b.w;
        acc[2][0] += a2 * b.x; acc[2][1] += a2 * b.y; acc[2][2] += a2 * b.z; acc[2][3] += a2 * b.w;
        acc[3][0] += a3 * b.x; acc[3][1] += a3 * b.y; acc[3][2] += a3 * b.z; acc[3][3] += a3 * b.w;
    }

    #pragma unroll
    for (int i = 0; i < 4; i++) {
        int row = row0 + ty * 4 + i;
        if (row < n) {
            float4 o;
            o.x = fmaxf(acc[i][0], 0.f);
            o.y = fmaxf(acc[i][1], 0.f);
            o.z = fmaxf(acc[i][2], 0.f);
            o.w = fmaxf(acc[i][3], 0.f);
            ((float4*)OUT)[(long long)row * 16 + tx] = o;
        }
    }
}

// ---------------- final GEMM: logits = H2 @ Wf[64,40] + bf ----------------
// Tile: 64 rows per block, 256 threads = 4 threads/row, 10 cols each.
__global__ __launch_bounds__(256) void gemm40_kernel(
    const float* __restrict__ H, const float* __restrict__ W,
    const float* __restrict__ B, float* __restrict__ OUT, int n)
{
    __shared__ float As[64][65];
    __shared__ float Ws[64][40];
    __shared__ float Bs[40];

    int t = threadIdx.x;
    int row0 = blockIdx.x * 64;

    #pragma unroll
    for (int i = 0; i < 4; i++) {
        int idx = t + i * 256;
        int r = idx >> 4;
        int c4 = idx & 15;
        int row = row0 + r;
        float4 hv = make_float4(0.f, 0.f, 0.f, 0.f);
        if (row < n) hv = ((const float4*)H)[(long long)row * 16 + c4];
        As[r][c4 * 4 + 0] = hv.x;
        As[r][c4 * 4 + 1] = hv.y;
        As[r][c4 * 4 + 2] = hv.z;
        As[r][c4 * 4 + 3] = hv.w;
    }
    for (int idx = t; idx < 64 * 40; idx += 256)
        Ws[idx / 40][idx % 40] = W[idx];
    if (t < 40) Bs[t] = B[t];
    __syncthreads();

    int tx = t & 3;         // col group: cols tx*10 .. tx*10+9
    int ty = t >> 2;        // row

    float acc[10];
    #pragma unroll
    for (int j = 0; j < 10; j++) acc[j] = Bs[tx * 10 + j];

    #pragma unroll
    for (int k = 0; k < 64; k++) {
        float a = As[ty][k];
        #pragma unroll
        for (int j = 0; j < 10; j++)
            acc[j] += a * Ws[k][tx * 10 + j];
    }

    int row = row0 + ty;
    if (row < n) {
        #pragma unroll
        for (int j = 0; j < 10; j++)
            OUT[(long long)row * NCLASS + tx * 10 + j] = acc[j];
    }
}

// ---------------- log_softmax in place on d_out, warp per row ----------------
__global__ void logsoftmax_kernel(float* __restrict__ L, int n) {
    int warp = (blockIdx.x * blockDim.x + threadIdx.x) >> 5;
    int lane = threadIdx.x & 31;
    if (warp >= n) return;
    float* row = L + (long long)warp * NCLASS;

    float v0 = (lane < NCLASS) ? row[lane] : -INFINITY;
    float v1 = (lane + 32 < NCLASS) ? row[lane + 32] : -INFINITY;

    float m = fmaxf(v0, v1);
    #pragma unroll
    for (int o = 16; o > 0; o >>= 1)
        m = fmaxf(m, __shfl_xor_sync(0xFFFFFFFFu, m, o));

    float s = 0.f;
    if (lane < NCLASS) s += __expf(v0 - m);
    if (lane + 32 < NCLASS) s += __expf(v1 - m);
    #pragma unroll
    for (int o = 16; o > 0; o >>= 1)
        s += __shfl_xor_sync(0xFFFFFFFFu, s, o);

    float ls = m + __logf(s);
    if (lane < NCLASS) row[lane] = v0 - ls;
    if (lane + 32 < NCLASS) row[lane + 32] = v1 - ls;
}

// ---------------- launch ----------------
extern "C" void kernel_launch(void* const* d_in, const int* in_sizes, int n_in,
                              void* d_out, int out_size) {
    const float* x  = (const float*)d_in[0];
    const void*  ei = d_in[1];
    const float* W1 = (const float*)d_in[2];
    const float* b1 = (const float*)d_in[3];
    const float* W2 = (const float*)d_in[4];
    const float* b2 = (const float*)d_in[5];
    const float* Wf = (const float*)d_in[6];
    const float* bf = (const float*)d_in[7];
    float* out = (float*)d_out;

    // device-global scratch addresses (query only; no allocation)
    float* agg; cudaGetSymbolAddress((void**)&agg, g_agg);
    float* h;   cudaGetSymbolAddress((void**)&h,   g_h);
    float* h2;  cudaGetSymbolAddress((void**)&h2,  g_h2);

    const int n = N_NODES;
    const int ZB = (N_NODES * 16 + 255) / 256;           // float4 count / 256
    const int SB = (int)(((long long)N_EDGES * 16 + 255) / 256);
    const int GB = (n + 63) / 64;
    const int LB = (n + 7) / 8;                          // 8 warps per block

    // edge preprocessing
    sniff_kernel<<<1, 256>>>((const unsigned int*)ei);
    convert_kernel<<<(N_EDGES + 255) / 256, 256>>>(ei);

    // ---- layer 1 ----
    zero_kernel<<<ZB, 256>>>((float4*)agg, N_NODES * 16);
    scatter_kernel<<<SB, 256>>>(x, agg);
    mlp64_kernel<<<GB, 256>>>(x, agg, W1, b1, h, n);

    // ---- layer 2 ----
    zero_kernel<<<ZB, 256>>>((float4*)agg, N_NODES * 16);
    scatter_kernel<<<SB, 256>>>(h, agg);
    mlp64_kernel<<<GB, 256>>>(h, agg, W2, b2, h2, n);

    // ---- classifier + log_softmax ----
    gemm40_kernel<<<GB, 256>>>(h2, Wf, bf, out, n);
    logsoftmax_kernel<<<LB, 256>>>(out, n);
}

// round 2
// speedup vs baseline: 1.1694x; 1.1694x over previous
#include <cuda_runtime.h>
#include <cuda_bf16.h>
#include <math.h>

#define N_NODES 100000
#define N_EDGES 1600000
#define NFEAT 64
#define NHID 64
#define NCLASS 40
#define SCAN_B 1024
#define SCAN_NB ((N_NODES + SCAN_B - 1) / SCAN_B)   // 98

// ---------------- device scratch (no allocations allowed) ----------------
__device__ int2  g_edges[N_EDGES];            // (src, dst) as int32
__device__ int   g_deg[N_NODES];
__device__ int   g_start[N_NODES + 1];        // CSR row offsets (by dst)
__device__ int   g_cursor[N_NODES];
__device__ int   g_bsum[128];
__device__ int   g_csr_src[N_EDGES];          // srcs grouped by dst
__device__ float g_h[N_NODES * NHID];         // layer-1 output
__device__ float g_h2[N_NODES * NHID];        // layer-2 output
__device__ int   g_is64;                      // edge_index dtype flag

// ---------------- dtype sniff: int64 vs int32 edge_index ----------------
__global__ void sniff_kernel(const unsigned int* __restrict__ w) {
    __shared__ int any;
    if (threadIdx.x == 0) any = 0;
    __syncthreads();
    unsigned int v = w[threadIdx.x * 2 + 1];
    if (v != 0u) atomicOr(&any, 1);
    __syncthreads();
    if (threadIdx.x == 0) g_is64 = (any == 0) ? 1 : 0;
}

__global__ void convert_kernel(const void* __restrict__ ei) {
    int e = blockIdx.x * blockDim.x + threadIdx.x;
    if (e >= N_EDGES) return;
    int s, d;
    if (g_is64) {
        const long long* p = (const long long*)ei;
        s = (int)p[e];
        d = (int)p[N_EDGES + e];
    } else {
        const int* p = (const int*)ei;
        s = p[e];
        d = p[N_EDGES + e];
    }
    g_edges[e] = make_int2(s, d);
}

// ---------------- CSR build ----------------
__global__ void zero_deg_kernel() {
    int i = blockIdx.x * blockDim.x + threadIdx.x;
    if (i < N_NODES) g_deg[i] = 0;
}

__global__ void hist_kernel() {
    int e = blockIdx.x * blockDim.x + threadIdx.x;
    if (e < N_EDGES) atomicAdd(&g_deg[g_edges[e].y], 1);
}

// pass 1: per-block exclusive scan (Hillis-Steele), block sums to g_bsum
__global__ __launch_bounds__(SCAN_B) void scan1_kernel() {
    __shared__ int sm[SCAN_B];
    int i = blockIdx.x * SCAN_B + threadIdx.x;
    int v = (i < N_NODES) ? g_deg[i] : 0;
    sm[threadIdx.x] = v;
    __syncthreads();
    #pragma unroll
    for (int o = 1; o < SCAN_B; o <<= 1) {
        int a = (threadIdx.x >= o) ? sm[threadIdx.x - o] : 0;
        __syncthreads();
        sm[threadIdx.x] += a;
        __syncthreads();
    }
    if (i < N_NODES) g_start[i] = sm[threadIdx.x] - v;   // exclusive within block
    if (threadIdx.x == SCAN_B - 1) g_bsum[blockIdx.x] = sm[SCAN_B - 1];
}

// pass 2: exclusive scan of the (<=98) block sums, single block of 128
__global__ void scan2_kernel() {
    __shared__ int sm[128];
    int v = (threadIdx.x < SCAN_NB) ? g_bsum[threadIdx.x] : 0;
    sm[threadIdx.x] = v;
    __syncthreads();
    #pragma unroll
    for (int o = 1; o < 128; o <<= 1) {
        int a = (threadIdx.x >= o) ? sm[threadIdx.x - o] : 0;
        __syncthreads();
        sm[threadIdx.x] += a;
        __syncthreads();
    }
    if (threadIdx.x < SCAN_NB) g_bsum[threadIdx.x] = sm[threadIdx.x] - v;
}

// pass 3: add block offsets; init cursor; cap sentinel
__global__ void scan3_kernel() {
    int i = blockIdx.x * blockDim.x + threadIdx.x;
    if (i < N_NODES) {
        int s = g_start[i] + g_bsum[i >> 10];
        g_start[i] = s;
        g_cursor[i] = s;
    }
    if (i == 0) g_start[N_NODES] = N_EDGES;
}

__global__ void fill_kernel() {
    int e = blockIdx.x * blockDim.x + threadIdx.x;
    if (e >= N_EDGES) return;
    int2 ed = g_edges[e];
    int pos = atomicAdd(&g_cursor[ed.y], 1);
    g_csr_src[pos] = ed.x;
}

// ---------------- fused gather + (X+AGG)@W + b + ReLU ----------------
// 256 threads, 64 nodes/block. Gather: 4 threads/node, each owns 16 cols,
// register accumulation over CSR neighbors (no atomics). Then 64x64 GEMM tile.
__global__ __launch_bounds__(256) void gin_layer_kernel(
    const float* __restrict__ X, const float* __restrict__ W,
    const float* __restrict__ B, float* __restrict__ OUT, int n)
{
    __shared__ float As[64][65];
    __shared__ __align__(16) float Ws[64][64];
    __shared__ float Bs[64];

    int t = threadIdx.x;
    int row0 = blockIdx.x * 64;

    // load weights up front (overlaps with gather latency)
    #pragma unroll
    for (int i = 0; i < 4; i++)
        ((float4*)Ws)[t + i * 256] = ((const float4*)W)[t + i * 256];
    if (t < 64) Bs[t] = B[t];

    // ---- gather phase ----
    int r = t >> 2;          // node within tile
    int q = t & 3;           // column quarter (16 floats)
    int row = row0 + r;
    float acc[16];

    if (row < n) {
        const float4* xp = (const float4*)X + (long long)row * 16 + q * 4;
        #pragma unroll
        for (int i = 0; i < 4; i++) {
            float4 v = xp[i];
            acc[4*i+0] = v.x; acc[4*i+1] = v.y; acc[4*i+2] = v.z; acc[4*i+3] = v.w;
        }
        int beg = g_start[row], end = g_start[row + 1];
        int j = beg;
        // unroll-2 over neighbors for extra MLP
        for (; j + 1 < end; j += 2) {
            int s0 = g_csr_src[j], s1 = g_csr_src[j + 1];
            const float4* p0 = (const float4*)X + (long long)s0 * 16 + q * 4;
            const float4* p1 = (const float4*)X + (long long)s1 * 16 + q * 4;
            float4 a0 = p0[0], a1 = p0[1], a2 = p0[2], a3 = p0[3];
            float4 b0 = p1[0], b1 = p1[1], b2 = p1[2], b3 = p1[3];
            acc[0]+=a0.x; acc[1]+=a0.y; acc[2]+=a0.z; acc[3]+=a0.w;
            acc[4]+=a1.x; acc[5]+=a1.y; acc[6]+=a1.z; acc[7]+=a1.w;
            acc[8]+=a2.x; acc[9]+=a2.y; acc[10]+=a2.z; acc[11]+=a2.w;
            acc[12]+=a3.x; acc[13]+=a3.y; acc[14]+=a3.z; acc[15]+=a3.w;
            acc[0]+=b0.x; acc[1]+=b0.y; acc[2]+=b0.z; acc[3]+=b0.w;
            acc[4]+=b1.x; acc[5]+=b1.y; acc[6]+=b1.z; acc[7]+=b1.w;
            acc[8]+=b2.x; acc[9]+=b2.y; acc[10]+=b2.z; acc[11]+=b2.w;
            acc[12]+=b3.x; acc[13]+=b3.y; acc[14]+=b3.z; acc[15]+=b3.w;
        }
        if (j < end) {
            int s0 = g_csr_src[j];
            const float4* p0 = (const float4*)X + (long long)s0 * 16 + q * 4;
            float4 a0 = p0[0], a1 = p0[1], a2 = p0[2], a3 = p0[3];
            acc[0]+=a0.x; acc[1]+=a0.y; acc[2]+=a0.z; acc[3]+=a0.w;
            acc[4]+=a1.x; acc[5]+=a1.y; acc[6]+=a1.z; acc[7]+=a1.w;
            acc[8]+=a2.x; acc[9]+=a2.y; acc[10]+=a2.z; acc[11]+=a2.w;
            acc[12]+=a3.x; acc[13]+=a3.y; acc[14]+=a3.z; acc[15]+=a3.w;
        }
    } else {
        #pragma unroll
        for (int i = 0; i < 16; i++) acc[i] = 0.f;
    }
    #pragma unroll
    for (int i = 0; i < 16; i++) As[r][q * 16 + i] = acc[i];
    __syncthreads();

    // ---- GEMM phase: 4x4 outputs per thread ----
    int tx = t & 15;
    int ty = t >> 4;

    float c[4][4];
    #pragma unroll
    for (int i = 0; i < 4; i++)
        #pragma unroll
        for (int jj = 0; jj < 4; jj++)
            c[i][jj] = Bs[tx * 4 + jj];

    #pragma unroll
    for (int k = 0; k < 64; k++) {
        float4 b = *(const float4*)&Ws[k][tx * 4];
        float a0 = As[ty * 4 + 0][k];
        float a1 = As[ty * 4 + 1][k];
        float a2 = As[ty * 4 + 2][k];
        float a3 = As[ty * 4 + 3][k];
        c[0][0] += a0 * b.x; c[0][1] += a0 * b.y; c[0][2] += a0 * b.z; c[0][3] += a0 * b.w;
        c[1][0] += a1 * b.x; c[1][1] += a1 * b.y; c[1][2] += a1 * b.z; c[1][3] += a1 * b.w;
        c[2][0] += a2 * b.x; c[2][1] += a2 * b.y; c[2][2] += a2 * b.z; c[2][3] += a2 * b.w;
        c[3][0] += a3 * b.x; c[3][1] += a3 * b.y; c[3][2] += a3 * b.z; c[3][3] += a3 * b.w;
    }

    #pragma unroll
    for (int i = 0; i < 4; i++) {
        int orow = row0 + ty * 4 + i;
        if (orow < n) {
            float4 o;
            o.x = fmaxf(c[i][0], 0.f);
            o.y = fmaxf(c[i][1], 0.f);
            o.z = fmaxf(c[i][2], 0.f);
            o.w = fmaxf(c[i][3], 0.f);
            ((float4*)OUT)[(long long)orow * 16 + tx] = o;
        }
    }
}

// ---------------- fused: logits = H2 @ Wf + bf, then log_softmax ----------------
// 64 rows/block, 4 threads/row (10 cols each), shfl reduce across the 4 lanes.
__global__ __launch_bounds__(256) void gemm40_ls_kernel(
    const float* __restrict__ H, const float* __restrict__ W,
    const float* __restrict__ B, float* __restrict__ OUT, int n)
{
    __shared__ float As[64][65];
    __shared__ float Ws[64][40];
    __shared__ float Bs[40];

    int t = threadIdx.x;
    int row0 = blockIdx.x * 64;

    #pragma unroll
    for (int i = 0; i < 4; i++) {
        int idx = t + i * 256;
        int r = idx >> 4;
        int c4 = idx & 15;
        int row = row0 + r;
        float4 hv = make_float4(0.f, 0.f, 0.f, 0.f);
        if (row < n) hv = ((const float4*)H)[(long long)row * 16 + c4];
        As[r][c4 * 4 + 0] = hv.x;
        As[r][c4 * 4 + 1] = hv.y;
        As[r][c4 * 4 + 2] = hv.z;
        As[r][c4 * 4 + 3] = hv.w;
    }
    for (int idx = t; idx < 64 * 40; idx += 256)
        Ws[idx / 40][idx % 40] = W[idx];
    if (t < 40) Bs[t] = B[t];
    __syncthreads();

    int tx = t & 3;
    int ty = t >> 2;

    float acc[10];
    #pragma unroll
    for (int j = 0; j < 10; j++) acc[j] = Bs[tx * 10 + j];

    #pragma unroll
    for (int k = 0; k < 64; k++) {
        float a = As[ty][k];
        #pragma unroll
        for (int j = 0; j < 10; j++)
            acc[j] += a * Ws[k][tx * 10 + j];
    }

    // log_softmax across the row's 40 logits (spread over 4 lanes)
    float m = acc[0];
    #pragma unroll
    for (int j = 1; j < 10; j++) m = fmaxf(m, acc[j]);
    m = fmaxf(m, __shfl_xor_sync(0xFFFFFFFFu, m, 1));
    m = fmaxf(m, __shfl_xor_sync(0xFFFFFFFFu, m, 2));

    float s = 0.f;
    #pragma unroll
    for (int j = 0; j < 10; j++) s += __expf(acc[j] - m);
    s += __shfl_xor_sync(0xFFFFFFFFu, s, 1);
    s += __shfl_xor_sync(0xFFFFFFFFu, s, 2);

    float ls = m + __logf(s);

    int row = row0 + ty;
    if (row < n) {
        #pragma unroll
        for (int j = 0; j < 10; j++)
            OUT[(long long)row * NCLASS + tx * 10 + j] = acc[j] - ls;
    }
}

// ---------------- launch ----------------
extern "C" void kernel_launch(void* const* d_in, const int* in_sizes, int n_in,
                              void* d_out, int out_size) {
    const float* x  = (const float*)d_in[0];
    const void*  ei = d_in[1];
    const float* W1 = (const float*)d_in[2];
    const float* b1 = (const float*)d_in[3];
    const float* W2 = (const float*)d_in[4];
    const float* b2 = (const float*)d_in[5];
    const float* Wf = (const float*)d_in[6];
    const float* bf = (const float*)d_in[7];
    float* out = (float*)d_out;

    float* h;   cudaGetSymbolAddress((void**)&h,   g_h);
    float* h2;  cudaGetSymbolAddress((void**)&h2,  g_h2);

    const int n = N_NODES;
    const int EB = (N_EDGES + 255) / 256;
    const int NB = (N_NODES + 255) / 256;
    const int GB = (n + 63) / 64;

    // edge preprocessing + CSR build
    sniff_kernel<<<1, 256>>>((const unsigned int*)ei);
    convert_kernel<<<EB, 256>>>(ei);
    zero_deg_kernel<<<NB, 256>>>();
    hist_kernel<<<EB, 256>>>();
    scan1_kernel<<<SCAN_NB, SCAN_B>>>();
    scan2_kernel<<<1, 128>>>();
    scan3_kernel<<<NB, 256>>>();
    fill_kernel<<<EB, 256>>>();

    // ---- layer 1 ----
    gin_layer_kernel<<<GB, 256>>>(x, W1, b1, h, n);
    // ---- layer 2 ----
    gin_layer_kernel<<<GB, 256>>>(h, W2, b2, h2, n);
    // ---- classifier + log_softmax ----
    gemm40_ls_kernel<<<GB, 256>>>(h2, Wf, bf, out, n);
}

// round 3
// speedup vs baseline: 1.5206x; 1.3003x over previous
#include <cuda_runtime.h>
#include <cuda_bf16.h>
#include <math.h>

#define N_NODES 100000
#define N_EDGES 1600000
#define NFEAT 64
#define NHID 64
#define NCLASS 40
#define SCAN_B 1024
#define SCAN_NB ((N_NODES + SCAN_B - 1) / SCAN_B)   // 98

// ---------------- device scratch (no allocations allowed) ----------------
__device__ int2  g_edges[N_EDGES];            // (src, dst) as int32
__device__ int   g_deg[N_NODES];
__device__ int   g_start[N_NODES + 1];        // CSR row offsets (by dst)
__device__ int   g_cursor[N_NODES];
__device__ int   g_bsum[128];
__device__ int   g_csr_src[N_EDGES];          // srcs grouped by dst
__device__ float g_h[N_NODES * NHID];         // layer-1 output
__device__ int   g_is64;                      // edge_index dtype flag

// ---------------- dtype sniff: int64 vs int32 edge_index ----------------
__global__ void sniff_kernel(const unsigned int* __restrict__ w) {
    __shared__ int any;
    if (threadIdx.x == 0) any = 0;
    __syncthreads();
    unsigned int v = w[threadIdx.x * 2 + 1];
    if (v != 0u) atomicOr(&any, 1);
    __syncthreads();
    if (threadIdx.x == 0) g_is64 = (any == 0) ? 1 : 0;
}

__global__ void zero_deg_kernel() {
    int i = blockIdx.x * blockDim.x + threadIdx.x;
    if (i < N_NODES) g_deg[i] = 0;
}

// fused: int64/int32 -> int2 conversion + degree histogram
__global__ void convert_hist_kernel(const void* __restrict__ ei) {
    int e = blockIdx.x * blockDim.x + threadIdx.x;
    if (e >= N_EDGES) return;
    int s, d;
    if (g_is64) {
        const long long* p = (const long long*)ei;
        s = (int)p[e];
        d = (int)p[N_EDGES + e];
    } else {
        const int* p = (const int*)ei;
        s = p[e];
        d = p[N_EDGES + e];
    }
    g_edges[e] = make_int2(s, d);
    atomicAdd(&g_deg[d], 1);
}

// pass 1: per-block exclusive scan (Hillis-Steele), block sums to g_bsum
__global__ __launch_bounds__(SCAN_B) void scan1_kernel() {
    __shared__ int sm[SCAN_B];
    int i = blockIdx.x * SCAN_B + threadIdx.x;
    int v = (i < N_NODES) ? g_deg[i] : 0;
    sm[threadIdx.x] = v;
    __syncthreads();
    #pragma unroll
    for (int o = 1; o < SCAN_B; o <<= 1) {
        int a = (threadIdx.x >= o) ? sm[threadIdx.x - o] : 0;
        __syncthreads();
        sm[threadIdx.x] += a;
        __syncthreads();
    }
    if (i < N_NODES) g_start[i] = sm[threadIdx.x] - v;
    if (threadIdx.x == SCAN_B - 1) g_bsum[blockIdx.x] = sm[SCAN_B - 1];
}

__global__ void scan2_kernel() {
    __shared__ int sm[128];
    int v = (threadIdx.x < SCAN_NB) ? g_bsum[threadIdx.x] : 0;
    sm[threadIdx.x] = v;
    __syncthreads();
    #pragma unroll
    for (int o = 1; o < 128; o <<= 1) {
        int a = (threadIdx.x >= o) ? sm[threadIdx.x - o] : 0;
        __syncthreads();
        sm[threadIdx.x] += a;
        __syncthreads();
    }
    if (threadIdx.x < SCAN_NB) g_bsum[threadIdx.x] = sm[threadIdx.x] - v;
}

__global__ void scan3_kernel() {
    int i = blockIdx.x * blockDim.x + threadIdx.x;
    if (i < N_NODES) {
        int s = g_start[i] + g_bsum[i >> 10];
        g_start[i] = s;
        g_cursor[i] = s;
    }
    if (i == 0) g_start[N_NODES] = N_EDGES;
}

__global__ void fill_kernel() {
    int e = blockIdx.x * blockDim.x + threadIdx.x;
    if (e >= N_EDGES) return;
    int2 ed = g_edges[e];
    int pos = atomicAdd(&g_cursor[ed.y], 1);
    g_csr_src[pos] = ed.x;
}

// ---------------- gather device helper ----------------
// Warp covers 2 rows (lanes 0-15 row A, 16-31 row B); each lane owns one
// float4 column chunk. Per neighbor: one contiguous 256B row read.
__device__ __forceinline__ float4 gather_row(const float4* __restrict__ X4,
                                             int row, int q, int n) {
    float4 acc = make_float4(0.f, 0.f, 0.f, 0.f);
    if (row >= n) return acc;
    acc = X4[(long long)row * 16 + q];
    int j = g_start[row], end = g_start[row + 1];
    for (; j + 3 < end; j += 4) {
        int s0 = g_csr_src[j], s1 = g_csr_src[j + 1];
        int s2 = g_csr_src[j + 2], s3 = g_csr_src[j + 3];
        float4 v0 = X4[(long long)s0 * 16 + q];
        float4 v1 = X4[(long long)s1 * 16 + q];
        float4 v2 = X4[(long long)s2 * 16 + q];
        float4 v3 = X4[(long long)s3 * 16 + q];
        acc.x += v0.x + v1.x + v2.x + v3.x;
        acc.y += v0.y + v1.y + v2.y + v3.y;
        acc.z += v0.z + v1.z + v2.z + v3.z;
        acc.w += v0.w + v1.w + v2.w + v3.w;
    }
    for (; j < end; j++) {
        float4 v = X4[(long long)g_csr_src[j] * 16 + q];
        acc.x += v.x; acc.y += v.y; acc.z += v.z; acc.w += v.w;
    }
    return acc;
}

// ---------------- layer 1: gather + (X+AGG)@W1 + b1 + ReLU -> g_h ----------------
__global__ __launch_bounds__(256) void gin_layer1_kernel(
    const float* __restrict__ X, const float* __restrict__ W,
    const float* __restrict__ B, float* __restrict__ OUT, int n)
{
    __shared__ float As[64][65];
    __shared__ __align__(16) float Ws[64][64];
    __shared__ float Bs[64];

    int t = threadIdx.x;
    int row0 = blockIdx.x * 64;
    int lane = t & 31, warp = t >> 5;

    #pragma unroll
    for (int i = 0; i < 4; i++)
        ((float4*)Ws)[t + i * 256] = ((const float4*)W)[t + i * 256];
    if (t < 64) Bs[t] = B[t];

    // gather: warp handles row pairs (rr, rr+1), 4 passes
    int half = lane >> 4;      // 0 or 1
    int q = lane & 15;         // float4 chunk
    const float4* X4 = (const float4*)X;
    #pragma unroll
    for (int pass = 0; pass < 4; pass++) {
        int r = warp * 2 + pass * 16 + half;
        float4 acc = gather_row(X4, row0 + r, q, n);
        As[r][q * 4 + 0] = acc.x;
        As[r][q * 4 + 1] = acc.y;
        As[r][q * 4 + 2] = acc.z;
        As[r][q * 4 + 3] = acc.w;
    }
    __syncthreads();

    // GEMM: 4x4 per thread
    int tx = t & 15, ty = t >> 4;
    float c[4][4];
    #pragma unroll
    for (int i = 0; i < 4; i++)
        #pragma unroll
        for (int jj = 0; jj < 4; jj++)
            c[i][jj] = Bs[tx * 4 + jj];

    #pragma unroll
    for (int k = 0; k < 64; k++) {
        float4 b = *(const float4*)&Ws[k][tx * 4];
        float a0 = As[ty * 4 + 0][k];
        float a1 = As[ty * 4 + 1][k];
        float a2 = As[ty * 4 + 2][k];
        float a3 = As[ty * 4 + 3][k];
        c[0][0] += a0 * b.x; c[0][1] += a0 * b.y; c[0][2] += a0 * b.z; c[0][3] += a0 * b.w;
        c[1][0] += a1 * b.x; c[1][1] += a1 * b.y; c[1][2] += a1 * b.z; c[1][3] += a1 * b.w;
        c[2][0] += a2 * b.x; c[2][1] += a2 * b.y; c[2][2] += a2 * b.z; c[2][3] += a2 * b.w;
        c[3][0] += a3 * b.x; c[3][1] += a3 * b.y; c[3][2] += a3 * b.z; c[3][3] += a3 * b.w;
    }

    #pragma unroll
    for (int i = 0; i < 4; i++) {
        int orow = row0 + ty * 4 + i;
        if (orow < n) {
            float4 o;
            o.x = fmaxf(c[i][0], 0.f);
            o.y = fmaxf(c[i][1], 0.f);
            o.z = fmaxf(c[i][2], 0.f);
            o.w = fmaxf(c[i][3], 0.f);
            ((float4*)OUT)[(long long)orow * 16 + tx] = o;
        }
    }
}

// ---------------- layer 2 + classifier + log_softmax, fully fused ----------------
// gather(h) -> (h+agg)@W2+b2,ReLU (h2 stays in smem) -> @Wf+bf -> log_softmax -> out
__global__ __launch_bounds__(256) void gin_layer2_final_kernel(
    const float* __restrict__ H, const float* __restrict__ W,
    const float* __restrict__ B, const float* __restrict__ WF,
    const float* __restrict__ BF, float* __restrict__ OUT, int n)
{
    __shared__ float As[64][65];
    __shared__ __align__(16) float Ws[64][64];
    __shared__ float Bs[64];
    __shared__ float Wf_s[64][40];
    __shared__ float Bf_s[40];

    int t = threadIdx.x;
    int row0 = blockIdx.x * 64;
    int lane = t & 31, warp = t >> 5;

    #pragma unroll
    for (int i = 0; i < 4; i++)
        ((float4*)Ws)[t + i * 256] = ((const float4*)W)[t + i * 256];
    if (t < 64) Bs[t] = B[t];
    for (int idx = t; idx < 64 * 40; idx += 256)
        Wf_s[idx / 40][idx % 40] = WF[idx];
    if (t < 40) Bf_s[t] = BF[t];

    // gather
    int half = lane >> 4;
    int q = lane & 15;
    const float4* H4 = (const float4*)H;
    #pragma unroll
    for (int pass = 0; pass < 4; pass++) {
        int r = warp * 2 + pass * 16 + half;
        float4 acc = gather_row(H4, row0 + r, q, n);
        As[r][q * 4 + 0] = acc.x;
        As[r][q * 4 + 1] = acc.y;
        As[r][q * 4 + 2] = acc.z;
        As[r][q * 4 + 3] = acc.w;
    }
    __syncthreads();

    // GEMM 1: h2 = relu((h+agg)@W2 + b2), kept in registers
    int tx = t & 15, ty = t >> 4;
    float c[4][4];
    #pragma unroll
    for (int i = 0; i < 4; i++)
        #pragma unroll
        for (int jj = 0; jj < 4; jj++)
            c[i][jj] = Bs[tx * 4 + jj];

    #pragma unroll
    for (int k = 0; k < 64; k++) {
        float4 b = *(const float4*)&Ws[k][tx * 4];
        float a0 = As[ty * 4 + 0][k];
        float a1 = As[ty * 4 + 1][k];
        float a2 = As[ty * 4 + 2][k];
        float a3 = As[ty * 4 + 3][k];
        c[0][0] += a0 * b.x; c[0][1] += a0 * b.y; c[0][2] += a0 * b.z; c[0][3] += a0 * b.w;
        c[1][0] += a1 * b.x; c[1][1] += a1 * b.y; c[1][2] += a1 * b.z; c[1][3] += a1 * b.w;
        c[2][0] += a2 * b.x; c[2][1] += a2 * b.y; c[2][2] += a2 * b.z; c[2][3] += a2 * b.w;
        c[3][0] += a3 * b.x; c[3][1] += a3 * b.y; c[3][2] += a3 * b.z; c[3][3] += a3 * b.w;
    }
    __syncthreads();   // everyone done reading As

    // restage relu(h2) into As
    #pragma unroll
    for (int i = 0; i < 4; i++) {
        int r = ty * 4 + i;
        As[r][tx * 4 + 0] = fmaxf(c[i][0], 0.f);
        As[r][tx * 4 + 1] = fmaxf(c[i][1], 0.f);
        As[r][tx * 4 + 2] = fmaxf(c[i][2], 0.f);
        As[r][tx * 4 + 3] = fmaxf(c[i][3], 0.f);
    }
    __syncthreads();

    // GEMM 2 + log_softmax: 4 threads/row, 10 cols each
    int tx4 = t & 3, ty4 = t >> 2;
    float acc[10];
    #pragma unroll
    for (int j = 0; j < 10; j++) acc[j] = Bf_s[tx4 * 10 + j];

    #pragma unroll
    for (int k = 0; k < 64; k++) {
        float a = As[ty4][k];
        #pragma unroll
        for (int j = 0; j < 10; j++)
            acc[j] += a * Wf_s[k][tx4 * 10 + j];
    }

    float m = acc[0];
    #pragma unroll
    for (int j = 1; j < 10; j++) m = fmaxf(m, acc[j]);
    m = fmaxf(m, __shfl_xor_sync(0xFFFFFFFFu, m, 1));
    m = fmaxf(m, __shfl_xor_sync(0xFFFFFFFFu, m, 2));

    float s = 0.f;
    #pragma unroll
    for (int j = 0; j < 10; j++) s += __expf(acc[j] - m);
    s += __shfl_xor_sync(0xFFFFFFFFu, s, 1);
    s += __shfl_xor_sync(0xFFFFFFFFu, s, 2);

    float ls = m + __logf(s);

    int row = row0 + ty4;
    if (row < n) {
        #pragma unroll
        for (int j = 0; j < 10; j++)
            OUT[(long long)row * NCLASS + tx4 * 10 + j] = acc[j] - ls;
    }
}

// ---------------- launch ----------------
extern "C" void kernel_launch(void* const* d_in, const int* in_sizes, int n_in,
                              void* d_out, int out_size) {
    const float* x  = (const float*)d_in[0];
    const void*  ei = d_in[1];
    const float* W1 = (const float*)d_in[2];
    const float* b1 = (const float*)d_in[3];
    const float* W2 = (const float*)d_in[4];
    const float* b2 = (const float*)d_in[5];
    const float* Wf = (const float*)d_in[6];
    const float* bf = (const float*)d_in[7];
    float* out = (float*)d_out;

    float* h; cudaGetSymbolAddress((void**)&h, g_h);

    const int n = N_NODES;
    const int EB = (N_EDGES + 255) / 256;
    const int NB = (N_NODES + 255) / 256;
    const int GB = (n + 63) / 64;

    // edge preprocessing + CSR build
    sniff_kernel<<<1, 256>>>((const unsigned int*)ei);
    zero_deg_kernel<<<NB, 256>>>();
    convert_hist_kernel<<<EB, 256>>>(ei);
    scan1_kernel<<<SCAN_NB, SCAN_B>>>();
    scan2_kernel<<<1, 128>>>();
    scan3_kernel<<<NB, 256>>>();
    fill_kernel<<<EB, 256>>>();

    // layer 1
    gin_layer1_kernel<<<GB, 256>>>(x, W1, b1, h, n);
    // layer 2 + classifier + log_softmax
    gin_layer2_final_kernel<<<GB, 256>>>(h, W2, b2, Wf, bf, out, n);
}